// round 1
// baseline (speedup 1.0000x reference)
#include <cuda_runtime.h>

#define T_STEPS 262144
#define HID 32

// Scratch (static __device__ arrays per harness rules — no cudaMalloc anywhere)
__device__ float4 g_xg[T_STEPS * HID];  // packed per-(t,k) gate preactivations (i,f,g,o)
__device__ float  g_h [T_STEPS * HID];  // h history

typedef unsigned long long u64;

__device__ __forceinline__ u64 pack2(float lo, float hi) {
    u64 r; asm("mov.b64 %0, {%1,%2};" : "=l"(r) : "f"(lo), "f"(hi)); return r;
}
__device__ __forceinline__ void unpack2(u64 v, float& lo, float& hi) {
    asm("mov.b64 {%0,%1}, %2;" : "=f"(lo), "=f"(hi) : "l"(v));
}
// Blackwell packed fp32 FMA: 2 MACs per instruction (ptxas never emits from C++)
__device__ __forceinline__ u64 fma2(u64 a, u64 b, u64 c) {
    u64 d; asm("fma.rn.f32x2 %0, %1, %2, %3;" : "=l"(d) : "l"(a), "l"(b), "l"(c)); return d;
}
__device__ __forceinline__ u64 add2(u64 a, u64 b) {
    u64 d; asm("add.rn.f32x2 %0, %1, %2;" : "=l"(d) : "l"(a), "l"(b)); return d;
}

__device__ __forceinline__ float fast_sigmoid(float x) {
    float e = __expf(-x);                      // MUFU.EX2 path, ~2 ulp
    return __fdividef(1.0f, 1.0f + e);         // MUFU.RCP path
}
__device__ __forceinline__ float fast_tanh(float x) {
    // tanh(|x|) = 1 - 2/(e^{2|x|}+1); safe for large |x| (e->inf -> 2/inf = 0)
    float e = __expf(2.0f * fabsf(x));
    float r = 1.0f - __fdividef(2.0f, 1.0f + e);
    return copysignf(r, x);
}

// ---------------------------------------------------------------------------
// Kernel 1: xg[t][k] = (i,f,g,o) input contributions + biases  (fully parallel)
// ---------------------------------------------------------------------------
__global__ void xg_kernel(const float* __restrict__ x,
                          const float* __restrict__ W_ih,
                          const float* __restrict__ b_ih,
                          const float* __restrict__ b_hh) {
    int idx = blockIdx.x * blockDim.x + threadIdx.x;  // = t*32 + k
    if (idx >= T_STEPS * HID) return;
    int t = idx >> 5;
    int k = idx & 31;
    float x0 = x[t * 3 + 0];
    float x1 = x[t * 3 + 1];
    float x2 = x[t * 3 + 2];
    float4 r;
    float* rp = reinterpret_cast<float*>(&r);
#pragma unroll
    for (int gidx = 0; gidx < 4; gidx++) {
        int row = k + gidx * HID;
        float v = b_ih[row] + b_hh[row];
        v = fmaf(W_ih[row * 3 + 0], x0, v);
        v = fmaf(W_ih[row * 3 + 1], x1, v);
        v = fmaf(W_ih[row * 3 + 2], x2, v);
        rp[gidx] = v;
    }
    g_xg[idx] = r;
}

// ---------------------------------------------------------------------------
// Kernel 2: the serial recurrence. ONE warp, zero barriers.
// Lane k owns h[k], c[k] and gate rows {k, k+32, k+64, k+96} of W_hh.
// ---------------------------------------------------------------------------
__global__ void __launch_bounds__(32, 1)
lstm_seq_kernel(const float* __restrict__ W_hh) {
    const int k = threadIdx.x;

    // Pack weights into f32x2 pairs, resident in registers for the whole run.
    u64 wi[16], wf[16], wg[16], wo[16];
#pragma unroll
    for (int j = 0; j < 16; j++) {
        float2 a;
        a = reinterpret_cast<const float2*>(W_hh + (k      ) * HID)[j]; wi[j] = pack2(a.x, a.y);
        a = reinterpret_cast<const float2*>(W_hh + (k + 32 ) * HID)[j]; wf[j] = pack2(a.x, a.y);
        a = reinterpret_cast<const float2*>(W_hh + (k + 64 ) * HID)[j]; wg[j] = pack2(a.x, a.y);
        a = reinterpret_cast<const float2*>(W_hh + (k + 96 ) * HID)[j]; wo[j] = pack2(a.x, a.y);
    }

    float h = 0.0f, c = 0.0f;

    // Register ring: prefetch xg 4 steps ahead (covers DRAM latency)
    float4 buf[4];
#pragma unroll
    for (int u = 0; u < 4; u++) buf[u] = g_xg[u * HID + k];

#pragma unroll 1
    for (int t = 0; t < T_STEPS; t += 4) {
#pragma unroll
        for (int u = 0; u < 4; u++) {
            float4 pg = buf[u];
            int pt = t + 4 + u;
            if (pt < T_STEPS) buf[u] = g_xg[pt * HID + k];  // fire-and-forget prefetch

            // gates = W_hh[rows] . h  via shuffle-broadcast + packed FMA
            u64 ai0 = 0, ai1 = 0, af0 = 0, af1 = 0;
            u64 ag0 = 0, ag1 = 0, ao0 = 0, ao1 = 0;
#pragma unroll
            for (int j = 0; j < 16; j++) {
                float h0 = __shfl_sync(0xffffffffu, h, 2 * j);
                float h1 = __shfl_sync(0xffffffffu, h, 2 * j + 1);
                u64 h2 = pack2(h0, h1);
                if (j & 1) {
                    ai1 = fma2(wi[j], h2, ai1); af1 = fma2(wf[j], h2, af1);
                    ag1 = fma2(wg[j], h2, ag1); ao1 = fma2(wo[j], h2, ao1);
                } else {
                    ai0 = fma2(wi[j], h2, ai0); af0 = fma2(wf[j], h2, af0);
                    ag0 = fma2(wg[j], h2, ag0); ao0 = fma2(wo[j], h2, ao0);
                }
            }
            float lo, hi;
            unpack2(add2(ai0, ai1), lo, hi); float pi  = pg.x + lo + hi;
            unpack2(add2(af0, af1), lo, hi); float pf  = pg.y + lo + hi;
            unpack2(add2(ag0, ag1), lo, hi); float pgt = pg.z + lo + hi;
            unpack2(add2(ao0, ao1), lo, hi); float po  = pg.w + lo + hi;

            float ig = fast_sigmoid(pi);
            float fg = fast_sigmoid(pf);
            float gg = fast_tanh(pgt);
            float og = fast_sigmoid(po);

            c = fmaf(fg, c, ig * gg);
            h = og * fast_tanh(c);

            g_h[(t + u) * HID + k] = h;  // coalesced 128B store, off critical path
        }
    }
}

// ---------------------------------------------------------------------------
// Kernel 3: y[t] = W_lin . h[t] + b_lin   (warp per t, shuffle reduce)
// ---------------------------------------------------------------------------
__global__ void out_kernel(const float* __restrict__ W_lin,
                           const float* __restrict__ b_lin,
                           float* __restrict__ y) {
    int warp = (blockIdx.x * blockDim.x + threadIdx.x) >> 5;
    int k = threadIdx.x & 31;
    if (warp >= T_STEPS) return;
    float p = W_lin[k] * g_h[warp * HID + k];
#pragma unroll
    for (int s = 16; s; s >>= 1) p += __shfl_xor_sync(0xffffffffu, p, s);
    if (k == 0) y[warp] = p + b_lin[0];
}

// ---------------------------------------------------------------------------
extern "C" void kernel_launch(void* const* d_in, const int* in_sizes, int n_in,
                              void* d_out, int out_size) {
    const float* x     = (const float*)d_in[0];
    const float* W_ih  = (const float*)d_in[1];
    const float* W_hh  = (const float*)d_in[2];
    const float* b_ih  = (const float*)d_in[3];
    const float* b_hh  = (const float*)d_in[4];
    const float* W_lin = (const float*)d_in[5];
    const float* b_lin = (const float*)d_in[6];
    float* y = (float*)d_out;

    int n = T_STEPS * HID;
    xg_kernel<<<(n + 255) / 256, 256>>>(x, W_ih, b_ih, b_hh);
    lstm_seq_kernel<<<1, 32>>>(W_hh);
    out_kernel<<<(n + 255) / 256, 256>>>(W_lin, b_lin, y);
}